// round 2
// baseline (speedup 1.0000x reference)
#include <cuda_runtime.h>
#include <cstdint>

#define BDIM 4
#define TDIM 4096
#define CDIM 1024
#define MDIM (BDIM*TDIM)          // 16384 rows
#define KDIM CDIM                 // 1024 reduction

// ---------------- scratch (static device globals; no allocation) -------------
__device__ float g_k[(size_t)MDIM*CDIM];   // k projection
__device__ float g_v[(size_t)MDIM*CDIM];   // v projection
__device__ float g_r[(size_t)MDIM*CDIM];   // sigmoid(r), then overwritten with r*wkv

// ---------------- tf32 helpers ----------------
__device__ __forceinline__ uint32_t f2tf(float x) {
    uint32_t u;
    asm("cvt.rna.tf32.f32 %0, %1;" : "=r"(u) : "f"(x));
    return u;
}

__device__ __forceinline__ void mma8(float* d, const uint32_t* a, const uint32_t* b) {
    asm volatile(
        "mma.sync.aligned.m16n8k8.row.col.f32.tf32.tf32.f32 "
        "{%0,%1,%2,%3}, {%4,%5,%6,%7}, {%8,%9}, {%0,%1,%2,%3};\n"
        : "+f"(d[0]), "+f"(d[1]), "+f"(d[2]), "+f"(d[3])
        : "r"(a[0]), "r"(a[1]), "r"(a[2]), "r"(a[3]), "r"(b[0]), "r"(b[1]));
}

// ---------------- GEMM: O[m,n] = sum_k A[m,k] * W[n,k]  (both K-major) -------
// 128x128 block tile, BK=16, double buffered, 8 warps, warp tile 64x32,
// m16n8k8 tf32. Smem row stride 20 words -> conflict-free fragment loads.
#define SSTR 20

__global__ __launch_bounds__(256)
void gemm_kernel(const float* __restrict__ X,
                 const float* __restrict__ W0, const float* __restrict__ W1,
                 const float* __restrict__ W2,
                 float* __restrict__ O0, float* __restrict__ O1, float* __restrict__ O2,
                 int sigmoid_wsel)
{
    __shared__ __align__(16) uint32_t As[2][128 * SSTR];
    __shared__ __align__(16) uint32_t Bs[2][128 * SSTR];

    const int tid  = threadIdx.x;
    const int lane = tid & 31;
    const int warp = tid >> 5;
    const int wm = warp >> 2;        // 0..1
    const int wn = warp & 3;         // 0..3
    const int g  = lane >> 2;        // 0..7
    const int tg = lane & 3;         // 0..3

    const int bm   = blockIdx.x;     // 0..127
    const int wsel = blockIdx.y >> 3;
    const int bn   = blockIdx.y & 7;

    const float* W = (wsel == 0) ? W0 : ((wsel == 1) ? W1 : W2);
    float*       O = (wsel == 0) ? O0 : ((wsel == 1) ? O1 : O2);

    // each thread: one row (tid>>1), two adjacent float4 (32B) per tile
    const int lrow = tid >> 1;
    const int half = tid & 1;
    const float4* Xg = reinterpret_cast<const float4*>(
        X + (size_t)(bm * 128 + lrow) * KDIM) + half * 2;
    const float4* Wg = reinterpret_cast<const float4*>(
        W + (size_t)(bn * 128 + lrow) * KDIM) + half * 2;
    const int sbase = lrow * SSTR + half * 8;

    float acc[4][4][4];
    #pragma unroll
    for (int mi = 0; mi < 4; ++mi)
        #pragma unroll
        for (int ni = 0; ni < 4; ++ni)
            #pragma unroll
            for (int rr = 0; rr < 4; ++rr) acc[mi][ni][rr] = 0.f;

    // prologue: tile 0
    float4 xa = Xg[0], xb = Xg[1], wa = Wg[0], wb = Wg[1];
    {
        uint4 ua = make_uint4(f2tf(xa.x), f2tf(xa.y), f2tf(xa.z), f2tf(xa.w));
        uint4 ub = make_uint4(f2tf(xb.x), f2tf(xb.y), f2tf(xb.z), f2tf(xb.w));
        *reinterpret_cast<uint4*>(&As[0][sbase])     = ua;
        *reinterpret_cast<uint4*>(&As[0][sbase + 4]) = ub;
        uint4 va = make_uint4(f2tf(wa.x), f2tf(wa.y), f2tf(wa.z), f2tf(wa.w));
        uint4 vb = make_uint4(f2tf(wb.x), f2tf(wb.y), f2tf(wb.z), f2tf(wb.w));
        *reinterpret_cast<uint4*>(&Bs[0][sbase])     = va;
        *reinterpret_cast<uint4*>(&Bs[0][sbase + 4]) = vb;
    }
    __syncthreads();

    int buf = 0;
    const int NT = KDIM / 16;  // 64 k-tiles
    for (int kt = 0; kt < NT; ++kt) {
        if (kt + 1 < NT) {
            xa = Xg[(kt + 1) * 4];
            xb = Xg[(kt + 1) * 4 + 1];
            wa = Wg[(kt + 1) * 4];
            wb = Wg[(kt + 1) * 4 + 1];
        }

        const uint32_t* Ab = As[buf];
        const uint32_t* Bb = Bs[buf];
        #pragma unroll
        for (int ks = 0; ks < 2; ++ks) {
            const int k0 = ks * 8;
            uint32_t af[4][4], bf[4][2];
            #pragma unroll
            for (int mi = 0; mi < 4; ++mi) {
                const int rm = wm * 64 + mi * 16;
                af[mi][0] = Ab[(rm + g)     * SSTR + k0 + tg];
                af[mi][1] = Ab[(rm + 8 + g) * SSTR + k0 + tg];
                af[mi][2] = Ab[(rm + g)     * SSTR + k0 + 4 + tg];
                af[mi][3] = Ab[(rm + 8 + g) * SSTR + k0 + 4 + tg];
            }
            #pragma unroll
            for (int ni = 0; ni < 4; ++ni) {
                const int rn = wn * 32 + ni * 8;
                bf[ni][0] = Bb[(rn + g) * SSTR + k0 + tg];
                bf[ni][1] = Bb[(rn + g) * SSTR + k0 + 4 + tg];
            }
            #pragma unroll
            for (int mi = 0; mi < 4; ++mi)
                #pragma unroll
                for (int ni = 0; ni < 4; ++ni)
                    mma8(acc[mi][ni], af[mi], bf[ni]);
        }

        if (kt + 1 < NT) {
            uint32_t* An = As[buf ^ 1];
            uint32_t* Bn = Bs[buf ^ 1];
            uint4 ua = make_uint4(f2tf(xa.x), f2tf(xa.y), f2tf(xa.z), f2tf(xa.w));
            uint4 ub = make_uint4(f2tf(xb.x), f2tf(xb.y), f2tf(xb.z), f2tf(xb.w));
            *reinterpret_cast<uint4*>(&An[sbase])     = ua;
            *reinterpret_cast<uint4*>(&An[sbase + 4]) = ub;
            uint4 va = make_uint4(f2tf(wa.x), f2tf(wa.y), f2tf(wa.z), f2tf(wa.w));
            uint4 vb = make_uint4(f2tf(wb.x), f2tf(wb.y), f2tf(wb.z), f2tf(wb.w));
            *reinterpret_cast<uint4*>(&Bn[sbase])     = va;
            *reinterpret_cast<uint4*>(&Bn[sbase + 4]) = vb;
            __syncthreads();
        }
        buf ^= 1;
    }

    // epilogue
    const bool do_sig = (wsel == sigmoid_wsel);
    #pragma unroll
    for (int mi = 0; mi < 4; ++mi) {
        #pragma unroll
        for (int ni = 0; ni < 4; ++ni) {
            const int row = bm * 128 + wm * 64 + mi * 16 + g;
            const int col = bn * 128 + wn * 32 + ni * 8 + tg * 2;
            float v0 = acc[mi][ni][0], v1 = acc[mi][ni][1];
            float v2 = acc[mi][ni][2], v3 = acc[mi][ni][3];
            if (do_sig) {
                v0 = 1.f / (1.f + __expf(-v0));
                v1 = 1.f / (1.f + __expf(-v1));
                v2 = 1.f / (1.f + __expf(-v2));
                v3 = 1.f / (1.f + __expf(-v3));
            }
            O[(size_t)row * CDIM + col]           = v0;
            O[(size_t)row * CDIM + col + 1]       = v1;
            O[(size_t)(row + 8) * CDIM + col]     = v2;
            O[(size_t)(row + 8) * CDIM + col + 1] = v3;
        }
    }
}

// ---------------- WKV scan: un-stabilized linear recurrence ------------------
// State kept as A = aa*e^{pp}, Bb = bb*e^{pp}. Then:
//   wkv_t = (A + e^{u+k_t} v_t) / (Bb + e^{u+k_t})
//   A' = e^{-w} A + e^{k_t} v_t ;  Bb' = e^{-w} Bb + e^{k_t}
// Final ref state: pp via max-recurrence, aa = A e^{-pp}, bb = Bb e^{-pp}.
__global__ void wkv_kernel(const float* __restrict__ K, const float* __restrict__ V,
                           float* __restrict__ R,
                           const float* __restrict__ td, const float* __restrict__ tf,
                           const float* __restrict__ aa0, const float* __restrict__ bb0,
                           const float* __restrict__ pp0,
                           float* __restrict__ st_aa, float* __restrict__ st_bb,
                           float* __restrict__ st_pp)
{
    const int idx = blockIdx.x * blockDim.x + threadIdx.x;   // 0..4095
    const int c = idx & (CDIM - 1);
    const float w = __expf(td[c]);
    const float u = tf[c];
    const float d = __expf(-w);

    const float p0  = pp0[idx];
    const float ep0 = __expf(p0);          // -1e38 -> 0
    float A  = aa0[idx] * ep0;
    float Bb = bb0[idx] * ep0;
    float pp = p0;

    size_t off = (size_t)(idx >> 10) * (size_t)TDIM * CDIM + c;
    #pragma unroll 8
    for (int t = 0; t < TDIM; ++t, off += CDIM) {
        const float kt = K[off];
        const float vt = V[off];
        const float rt = R[off];
        const float eku = __expf(u + kt);
        const float wkv = __fdividef(__fmaf_rn(eku, vt, A), Bb + eku);
        R[off] = rt * wkv;                 // fuse r * wkv for output GEMM
        const float ek = __expf(kt);
        A  = __fmaf_rn(d, A, ek * vt);
        Bb = __fmaf_rn(d, Bb, ek);
        pp = fmaxf(pp - w, kt);
    }

    if (st_aa) {
        const float e = __expf(-pp);
        st_aa[idx] = A * e;
        st_bb[idx] = Bb * e;
        st_pp[idx] = pp;
    }
}

// ---------------- launch ----------------
extern "C" void kernel_launch(void* const* d_in, const int* in_sizes, int n_in,
                              void* d_out, int out_size)
{
    const float* x   = (const float*)d_in[0];
    const float* kw  = (const float*)d_in[1];
    const float* vw  = (const float*)d_in[2];
    const float* rw  = (const float*)d_in[3];
    const float* ow  = (const float*)d_in[4];
    const float* td  = (const float*)d_in[5];
    const float* tfi = (const float*)d_in[6];
    const float* aa0 = (const float*)d_in[7];
    const float* bb0 = (const float*)d_in[8];
    const float* pp0 = (const float*)d_in[9];
    float* out = (float*)d_out;

    void *pk, *pv, *pr;
    cudaGetSymbolAddress(&pk, g_k);
    cudaGetSymbolAddress(&pv, g_v);
    cudaGetSymbolAddress(&pr, g_r);
    float* gk = (float*)pk;
    float* gv = (float*)pv;
    float* gr = (float*)pr;

    const long long BTC = (long long)MDIM * CDIM;          // 16777216
    const int BC = BDIM * CDIM;                            // 4096
    const bool write_states = ((long long)out_size >= BTC + 3LL * BC);
    float* staa = write_states ? out + BTC            : nullptr;
    float* stbb = write_states ? out + BTC + BC       : nullptr;
    float* stpp = write_states ? out + BTC + 2 * BC   : nullptr;

    // 1) fused k / v / sigmoid(r) projections
    dim3 gp(MDIM / 128, 24);
    gemm_kernel<<<gp, 256>>>(x, kw, vw, rw, gk, gv, gr, /*sigmoid_wsel=*/2);

    // 2) WKV scan (+ r*wkv in place, + final states)
    wkv_kernel<<<BC / 64, 64>>>(gk, gv, gr, td, tfi, aa0, bb0, pp0,
                                staa, stbb, stpp);

    // 3) output projection
    dim3 go(MDIM / 128, 8);
    gemm_kernel<<<go, 256>>>(gr, ow, ow, ow, out, out, out, /*sigmoid_wsel=*/-1);
}

// round 3
// speedup vs baseline: 1.7424x; 1.7424x over previous
#include <cuda_runtime.h>
#include <cstdint>

#define BDIM 4
#define TDIM 4096
#define CDIM 1024
#define MDIM (BDIM*TDIM)          // 16384 rows
#define KDIM CDIM                 // 1024 reduction
#define NCH  64                   // scan chunks
#define CLEN 64                   // steps per chunk (NCH*CLEN == TDIM)
#define NC   (BDIM*CDIM)          // 4096 channels

// ---------------- scratch (static device globals; no allocation) -------------
__device__ float g_k[(size_t)MDIM*CDIM];   // k projection
__device__ float g_v[(size_t)MDIM*CDIM];   // v projection
__device__ float g_r[(size_t)MDIM*CDIM];   // sigmoid(r), then overwritten with r*wkv
// per-(channel,chunk) scan scratch: layout [b][chunk][c] -> b*65536 + j*1024 + c
__device__ float g_Aloc[NC*NCH], g_Bloc[NC*NCH], g_Mloc[NC*NCH];
__device__ float g_Ain [NC*NCH], g_Bin [NC*NCH];

// ---------------- tf32 helpers ----------------
__device__ __forceinline__ uint32_t f2tf(float x) {
    uint32_t u;
    asm("cvt.rna.tf32.f32 %0, %1;" : "=r"(u) : "f"(x));
    return u;
}

__device__ __forceinline__ void mma8(float* d, const uint32_t* a, const uint32_t* b) {
    asm volatile(
        "mma.sync.aligned.m16n8k8.row.col.f32.tf32.tf32.f32 "
        "{%0,%1,%2,%3}, {%4,%5,%6,%7}, {%8,%9}, {%0,%1,%2,%3};\n"
        : "+f"(d[0]), "+f"(d[1]), "+f"(d[2]), "+f"(d[3])
        : "r"(a[0]), "r"(a[1]), "r"(a[2]), "r"(a[3]), "r"(b[0]), "r"(b[1]));
}

// ---------------- GEMM: O[m,n] = sum_k A[m,k] * W[n,k]  (both K-major) -------
// 128x128 block tile, BK=16, double buffered, 8 warps, warp tile 64x32.
// Fragment loads use the k-permutation trick: thread tg loads physical columns
// (k0+2tg, k0+2tg+1) for BOTH A and B as one 64-bit LDS. Dot product is
// invariant under k permutation, so the result is exact. SSTR=24 makes the
// 64-bit loads bank-conflict-free (g*24 mod 32 in {0,24,16,8} per phase).
#define SSTR 24

__global__ __launch_bounds__(256)
void gemm_kernel(const float* __restrict__ X,
                 const float* __restrict__ W0, const float* __restrict__ W1,
                 const float* __restrict__ W2,
                 float* __restrict__ O0, float* __restrict__ O1, float* __restrict__ O2,
                 int sigmoid_wsel)
{
    __shared__ __align__(16) uint32_t As[2][128 * SSTR];
    __shared__ __align__(16) uint32_t Bs[2][128 * SSTR];

    const int tid  = threadIdx.x;
    const int lane = tid & 31;
    const int warp = tid >> 5;
    const int wm = warp >> 2;        // 0..1
    const int wn = warp & 3;         // 0..3
    const int g  = lane >> 2;        // 0..7
    const int tg = lane & 3;         // 0..3

    const int bm   = blockIdx.x;     // 0..127
    const int wsel = blockIdx.y >> 3;
    const int bn   = blockIdx.y & 7;

    const float* W = (wsel == 0) ? W0 : ((wsel == 1) ? W1 : W2);
    float*       O = (wsel == 0) ? O0 : ((wsel == 1) ? O1 : O2);

    // each thread: one row (tid>>1), two adjacent float4 (32B) per tile
    const int lrow = tid >> 1;
    const int half = tid & 1;
    const float4* Xg = reinterpret_cast<const float4*>(
        X + (size_t)(bm * 128 + lrow) * KDIM) + half * 2;
    const float4* Wg = reinterpret_cast<const float4*>(
        W + (size_t)(bn * 128 + lrow) * KDIM) + half * 2;
    const int sbase = lrow * SSTR + half * 8;

    float acc[4][4][4];
    #pragma unroll
    for (int mi = 0; mi < 4; ++mi)
        #pragma unroll
        for (int ni = 0; ni < 4; ++ni)
            #pragma unroll
            for (int rr = 0; rr < 4; ++rr) acc[mi][ni][rr] = 0.f;

    // prologue: tile 0
    float4 xa = Xg[0], xb = Xg[1], wa = Wg[0], wb = Wg[1];
    {
        uint4 ua = make_uint4(f2tf(xa.x), f2tf(xa.y), f2tf(xa.z), f2tf(xa.w));
        uint4 ub = make_uint4(f2tf(xb.x), f2tf(xb.y), f2tf(xb.z), f2tf(xb.w));
        *reinterpret_cast<uint4*>(&As[0][sbase])     = ua;
        *reinterpret_cast<uint4*>(&As[0][sbase + 4]) = ub;
        uint4 va = make_uint4(f2tf(wa.x), f2tf(wa.y), f2tf(wa.z), f2tf(wa.w));
        uint4 vb = make_uint4(f2tf(wb.x), f2tf(wb.y), f2tf(wb.z), f2tf(wb.w));
        *reinterpret_cast<uint4*>(&Bs[0][sbase])     = va;
        *reinterpret_cast<uint4*>(&Bs[0][sbase + 4]) = vb;
    }
    __syncthreads();

    int buf = 0;
    const int NT = KDIM / 16;  // 64 k-tiles
    for (int kt = 0; kt < NT; ++kt) {
        if (kt + 1 < NT) {
            xa = Xg[(kt + 1) * 4];
            xb = Xg[(kt + 1) * 4 + 1];
            wa = Wg[(kt + 1) * 4];
            wb = Wg[(kt + 1) * 4 + 1];
        }

        const uint32_t* Ab = As[buf];
        const uint32_t* Bb = Bs[buf];
        #pragma unroll
        for (int ks = 0; ks < 2; ++ks) {
            const int k0 = ks * 8;
            uint32_t af[4][4], bf[4][2];
            const int kc = k0 + 2 * tg;   // physical column pair start
            #pragma unroll
            for (int mi = 0; mi < 4; ++mi) {
                const int rm = wm * 64 + mi * 16;
                uint2 p0 = *reinterpret_cast<const uint2*>(&Ab[(rm + g)     * SSTR + kc]);
                uint2 p1 = *reinterpret_cast<const uint2*>(&Ab[(rm + 8 + g) * SSTR + kc]);
                af[mi][0] = p0.x; af[mi][2] = p0.y;
                af[mi][1] = p1.x; af[mi][3] = p1.y;
            }
            #pragma unroll
            for (int ni = 0; ni < 4; ++ni) {
                const int rn = wn * 32 + ni * 8;
                uint2 pb = *reinterpret_cast<const uint2*>(&Bb[(rn + g) * SSTR + kc]);
                bf[ni][0] = pb.x; bf[ni][1] = pb.y;
            }
            #pragma unroll
            for (int mi = 0; mi < 4; ++mi)
                #pragma unroll
                for (int ni = 0; ni < 4; ++ni)
                    mma8(acc[mi][ni], af[mi], bf[ni]);
        }

        if (kt + 1 < NT) {
            uint32_t* An = As[buf ^ 1];
            uint32_t* Bn = Bs[buf ^ 1];
            uint4 ua = make_uint4(f2tf(xa.x), f2tf(xa.y), f2tf(xa.z), f2tf(xa.w));
            uint4 ub = make_uint4(f2tf(xb.x), f2tf(xb.y), f2tf(xb.z), f2tf(xb.w));
            *reinterpret_cast<uint4*>(&An[sbase])     = ua;
            *reinterpret_cast<uint4*>(&An[sbase + 4]) = ub;
            uint4 va = make_uint4(f2tf(wa.x), f2tf(wa.y), f2tf(wa.z), f2tf(wa.w));
            uint4 vb = make_uint4(f2tf(wb.x), f2tf(wb.y), f2tf(wb.z), f2tf(wb.w));
            *reinterpret_cast<uint4*>(&Bn[sbase])     = va;
            *reinterpret_cast<uint4*>(&Bn[sbase + 4]) = vb;
            __syncthreads();
        }
        buf ^= 1;
    }

    // epilogue
    const bool do_sig = (wsel == sigmoid_wsel);
    #pragma unroll
    for (int mi = 0; mi < 4; ++mi) {
        #pragma unroll
        for (int ni = 0; ni < 4; ++ni) {
            const int row = bm * 128 + wm * 64 + mi * 16 + g;
            const int col = bn * 128 + wn * 32 + ni * 8 + tg * 2;
            float v0 = acc[mi][ni][0], v1 = acc[mi][ni][1];
            float v2 = acc[mi][ni][2], v3 = acc[mi][ni][3];
            if (do_sig) {
                v0 = 1.f / (1.f + __expf(-v0));
                v1 = 1.f / (1.f + __expf(-v1));
                v2 = 1.f / (1.f + __expf(-v2));
                v3 = 1.f / (1.f + __expf(-v3));
            }
            O[(size_t)row * CDIM + col]           = v0;
            O[(size_t)row * CDIM + col + 1]       = v1;
            O[(size_t)(row + 8) * CDIM + col]     = v2;
            O[(size_t)(row + 8) * CDIM + col + 1] = v3;
        }
    }
}

// ---------------- WKV chunked scan ------------------------------------------
// Un-stabilized linear recurrence: A' = d*A + e^k v ; B' = d*B + e^k
//   wkv_t = (A + e^{u+k} v)/(B + e^{u+k}),  d = e^{-w}, w = e^{time_decay}
// Chunked over T: pass1 computes per-chunk local sums, combine does the tiny
// sequential chunk-prefix per channel, pass2 re-scans with correct init state.

// Pass 1: local sums per (b, chunk, c). tix = b*65536 + j*1024 + c.
__global__ void wkv_pass1(const float* __restrict__ K, const float* __restrict__ V,
                          const float* __restrict__ td)
{
    const int tix = blockIdx.x * blockDim.x + threadIdx.x;
    const int c = tix & (CDIM - 1);
    const int j = (tix >> 10) & (NCH - 1);
    const int b = tix >> 16;
    const float w = __expf(td[c]);
    const float d = __expf(-w);

    float A = 0.f, Bb = 0.f, m = -3.0e38f;
    size_t off = (size_t)b * TDIM * CDIM + (size_t)j * CLEN * CDIM + c;
    #pragma unroll 8
    for (int t = 0; t < CLEN; ++t, off += CDIM) {
        const float kt = K[off];
        const float vt = V[off];
        const float ek = __expf(kt);
        A  = __fmaf_rn(d, A, ek * vt);
        Bb = __fmaf_rn(d, Bb, ek);
        m  = fmaxf(m - w, kt);
    }
    g_Aloc[tix] = A;
    g_Bloc[tix] = Bb;
    g_Mloc[tix] = m;
}

// Combine: one thread per channel; sequential prefix over 64 chunks.
__global__ void wkv_combine(const float* __restrict__ td,
                            const float* __restrict__ aa0, const float* __restrict__ bb0,
                            const float* __restrict__ pp0,
                            float* __restrict__ st_aa, float* __restrict__ st_bb,
                            float* __restrict__ st_pp)
{
    const int idx = blockIdx.x * blockDim.x + threadIdx.x;   // 0..4095
    const int c = idx & (CDIM - 1);
    const int b = idx >> 10;
    const float w  = __expf(td[c]);
    const float dL = __expf(-w * (float)CLEN);
    const float pL = w * (float)CLEN;

    const float p0 = pp0[idx];
    const float e0 = __expf(p0);           // -1e38 -> 0
    float A  = aa0[idx] * e0;
    float Bb = bb0[idx] * e0;
    float pp = p0;

    const int base = b * (NCH * CDIM) + c;
    #pragma unroll 4
    for (int j = 0; j < NCH; ++j) {
        const int s = base + j * CDIM;
        g_Ain[s] = A;
        g_Bin[s] = Bb;
        A  = __fmaf_rn(dL, A,  g_Aloc[s]);
        Bb = __fmaf_rn(dL, Bb, g_Bloc[s]);
        pp = fmaxf(pp - pL, g_Mloc[s]);
    }
    if (st_aa) {
        const float e = __expf(-pp);
        st_aa[idx] = A * e;
        st_bb[idx] = Bb * e;
        st_pp[idx] = pp;
    }
}

// Pass 2: re-scan each chunk with its initial state; write r*wkv in place.
__global__ void wkv_pass2(const float* __restrict__ K, const float* __restrict__ V,
                          float* __restrict__ R,
                          const float* __restrict__ td, const float* __restrict__ tf)
{
    const int tix = blockIdx.x * blockDim.x + threadIdx.x;
    const int c = tix & (CDIM - 1);
    const int j = (tix >> 10) & (NCH - 1);
    const int b = tix >> 16;
    const float w = __expf(td[c]);
    const float u = tf[c];
    const float d = __expf(-w);

    float A  = g_Ain[tix];
    float Bb = g_Bin[tix];

    size_t off = (size_t)b * TDIM * CDIM + (size_t)j * CLEN * CDIM + c;
    #pragma unroll 8
    for (int t = 0; t < CLEN; ++t, off += CDIM) {
        const float kt = K[off];
        const float vt = V[off];
        const float rt = R[off];
        const float eku = __expf(u + kt);
        const float wkv = __fdividef(__fmaf_rn(eku, vt, A), Bb + eku);
        R[off] = rt * wkv;
        const float ek = __expf(kt);
        A  = __fmaf_rn(d, A, ek * vt);
        Bb = __fmaf_rn(d, Bb, ek);
    }
}

// ---------------- launch ----------------
extern "C" void kernel_launch(void* const* d_in, const int* in_sizes, int n_in,
                              void* d_out, int out_size)
{
    const float* x   = (const float*)d_in[0];
    const float* kw  = (const float*)d_in[1];
    const float* vw  = (const float*)d_in[2];
    const float* rw  = (const float*)d_in[3];
    const float* ow  = (const float*)d_in[4];
    const float* td  = (const float*)d_in[5];
    const float* tfi = (const float*)d_in[6];
    const float* aa0 = (const float*)d_in[7];
    const float* bb0 = (const float*)d_in[8];
    const float* pp0 = (const float*)d_in[9];
    float* out = (float*)d_out;

    void *pk, *pv, *pr;
    cudaGetSymbolAddress(&pk, g_k);
    cudaGetSymbolAddress(&pv, g_v);
    cudaGetSymbolAddress(&pr, g_r);
    float* gk = (float*)pk;
    float* gv = (float*)pv;
    float* gr = (float*)pr;

    const long long BTC = (long long)MDIM * CDIM;          // 16777216
    const int BC = NC;                                     // 4096
    const bool write_states = ((long long)out_size >= BTC + 3LL * BC);
    float* staa = write_states ? out + BTC            : nullptr;
    float* stbb = write_states ? out + BTC + BC       : nullptr;
    float* stpp = write_states ? out + BTC + 2 * BC   : nullptr;

    // 1) fused k / v / sigmoid(r) projections
    dim3 gp(MDIM / 128, 24);
    gemm_kernel<<<gp, 256>>>(x, kw, vw, rw, gk, gv, gr, /*sigmoid_wsel=*/2);

    // 2) WKV chunked scan (+ r*wkv in place, + final states)
    wkv_pass1 <<<(NC * NCH) / 256, 256>>>(gk, gv, td);
    wkv_combine<<<NC / 256, 256>>>(td, aa0, bb0, pp0, staa, stbb, stpp);
    wkv_pass2 <<<(NC * NCH) / 256, 256>>>(gk, gv, gr, td, tfi);

    // 3) output projection
    dim3 go(MDIM / 128, 8);
    gemm_kernel<<<go, 256>>>(gr, ow, ow, ow, out, out, out, /*sigmoid_wsel=*/-1);
}

// round 6
// speedup vs baseline: 2.1829x; 1.2528x over previous
#include <cuda_runtime.h>
#include <cstdint>

#define BDIM 4
#define TDIM 4096
#define CDIM 1024
#define MDIM (BDIM*TDIM)          // 16384 rows
#define KDIM CDIM                 // 1024 reduction
#define NCH  64                   // scan chunks
#define CLEN 64                   // steps per chunk
#define NC   (BDIM*CDIM)          // 4096 channels

// GEMM tiling: block 128x256, 8 warps, warp tile 64x64, BK=32, 2-stage cp.async
#define TM 128
#define TN 256
#define TBK 32
#define NT (KDIM/TBK)             // 32 k-tiles
#define ROWB 192                  // smem bytes per row (48 words; conflict-free LDS.128)
#define STA (TM*ROWB)             // 24576 per A stage
#define STB (TN*ROWB)             // 49152 per B stage
#define DYN_SMEM (2*STA + 2*STB)  // 147456

// ---------------- scratch (static device globals; no allocation) -------------
__device__ float g_k[(size_t)MDIM*CDIM];
__device__ float g_v[(size_t)MDIM*CDIM];
__device__ float g_r[(size_t)MDIM*CDIM];
__device__ float g_x[(size_t)MDIM*CDIM];          // tf32-rounded x
__device__ float g_w[4*(size_t)CDIM*CDIM];        // tf32-rounded kw,vw,rw,ow
__device__ float g_Aloc[NC*NCH], g_Bloc[NC*NCH], g_Mloc[NC*NCH];
__device__ float g_Ain [NC*NCH], g_Bin [NC*NCH];

// ---------------- helpers ----------------
__device__ __forceinline__ uint32_t smem_u32(const void* p) {
    uint32_t a;
    asm("{ .reg .u64 t; cvta.to.shared.u64 t, %1; cvt.u32.u64 %0, t; }" : "=r"(a) : "l"(p));
    return a;
}
__device__ __forceinline__ uint32_t f2tf(float x) {
    uint32_t u;
    asm("cvt.rna.tf32.f32 %0, %1;" : "=r"(u) : "f"(x));
    return u;
}
__device__ __forceinline__ float f2tff(float x) {
    return __uint_as_float(f2tf(x));
}
__device__ __forceinline__ void mma8(float* d, const uint32_t* a, const uint32_t* b) {
    asm volatile(
        "mma.sync.aligned.m16n8k8.row.col.f32.tf32.tf32.f32 "
        "{%0,%1,%2,%3}, {%4,%5,%6,%7}, {%8,%9}, {%0,%1,%2,%3};\n"
        : "+f"(d[0]), "+f"(d[1]), "+f"(d[2]), "+f"(d[3])
        : "r"(a[0]), "r"(a[1]), "r"(a[2]), "r"(a[3]), "r"(b[0]), "r"(b[1]));
}
__device__ __forceinline__ uint4 lds128(uint32_t a) {
    uint4 v;
    asm volatile("ld.shared.v4.b32 {%0,%1,%2,%3}, [%4];"
                 : "=r"(v.x), "=r"(v.y), "=r"(v.z), "=r"(v.w) : "r"(a));
    return v;
}
#define CP_ASYNC16(sa, ga) \
    asm volatile("cp.async.cg.shared.global [%0], [%1], 16;" :: "r"(sa), "l"(ga))
#define CP_COMMIT() asm volatile("cp.async.commit_group;" ::: "memory")
#define CP_WAIT1()  asm volatile("cp.async.wait_group 1;" ::: "memory")
#define CP_WAIT0()  asm volatile("cp.async.wait_group 0;" ::: "memory")

// ---------------- pre-round to tf32 (rna) ------------------------------------
__global__ void conv_tf32(const float* __restrict__ in, float* __restrict__ out, int n4)
{
    const int i = blockIdx.x * blockDim.x + threadIdx.x;
    if (i < n4) {
        float4 v = reinterpret_cast<const float4*>(in)[i];
        v.x = f2tff(v.x); v.y = f2tff(v.y); v.z = f2tff(v.z); v.w = f2tff(v.w);
        reinterpret_cast<float4*>(out)[i] = v;
    }
}

// ---------------- GEMM: O[m,n] = sum_k A[m,k] * W[n,k]  (pre-rounded tf32) ---
// cp.async double-buffer, LDS.128 frags with k-permutation (lane tg covers
// physical cols k0+4tg..+3 for both A and B; dot product is k-permutation
// invariant so the result is exact).
__global__ __launch_bounds__(256)
void gemm_tc(const float* __restrict__ X,
             const float* __restrict__ W0, const float* __restrict__ W1,
             const float* __restrict__ W2,
             float* __restrict__ O0, float* __restrict__ O1, float* __restrict__ O2,
             int sigmoid_wsel)
{
    extern __shared__ char dyn[];
    const uint32_t sb = smem_u32(dyn);
    const uint32_t smA[2] = {sb, sb + STA};
    const uint32_t smB[2] = {sb + 2*STA, sb + 2*STA + STB};

    const int tid  = threadIdx.x;
    const int lane = tid & 31;
    const int warp = tid >> 5;
    const int wm = warp >> 2;        // 0..1
    const int wn = warp & 3;         // 0..3
    const int g  = lane >> 2;        // 0..7
    const int tg = lane & 3;         // 0..3

    const int bm   = blockIdx.x;
    const int wsel = blockIdx.y >> 2;
    const int bn   = blockIdx.y & 3;

    const float* Wm = (wsel == 0) ? W0 : ((wsel == 1) ? W1 : W2);
    float*       O  = (wsel == 0) ? O0 : ((wsel == 1) ? O1 : O2);

    const float* Xt = X  + (size_t)bm * TM * KDIM;
    const float* Bt = Wm + (size_t)bn * TN * KDIM;

    float acc[4][8][4];
    #pragma unroll
    for (int mi = 0; mi < 4; ++mi)
        #pragma unroll
        for (int ni = 0; ni < 8; ++ni)
            #pragma unroll
            for (int rr = 0; rr < 4; ++rr) acc[mi][ni][rr] = 0.f;

    // --- async load of one k-tile into buffer ---
    const int arow = tid >> 3;        // thread handles rows arow, arow+32, ...
    const int ach  = (tid & 7) * 16;  // 16B chunk offset within row
    auto issue = [&](int kt, int buf) {
        const float* gx = Xt + (size_t)arow * KDIM + kt * TBK + (tid & 7) * 4;
        uint32_t sa = smA[buf] + arow * ROWB + ach;
        #pragma unroll
        for (int i = 0; i < 4; ++i)
            CP_ASYNC16(sa + i * (32 * ROWB), gx + (size_t)(i * 32) * KDIM);
        const float* gb = Bt + (size_t)arow * KDIM + kt * TBK + (tid & 7) * 4;
        uint32_t sbb = smB[buf] + arow * ROWB + ach;
        #pragma unroll
        for (int i = 0; i < 8; ++i)
            CP_ASYNC16(sbb + i * (32 * ROWB), gb + (size_t)(i * 32) * KDIM);
    };

    issue(0, 0); CP_COMMIT();
    issue(1, 1); CP_COMMIT();

    for (int kt = 0; kt < NT; ++kt) {
        const int buf = kt & 1;
        if (kt + 1 < NT) CP_WAIT1(); else CP_WAIT0();
        __syncthreads();

        const uint32_t Ab = smA[buf];
        const uint32_t Bb = smB[buf];
        #pragma unroll
        for (int kg = 0; kg < 2; ++kg) {
            const uint32_t kb = (uint32_t)(kg * 64 + tg * 16);  // byte offset in row
            uint4 aq0[4], aq1[4];
            #pragma unroll
            for (int mi = 0; mi < 4; ++mi) {
                const uint32_t r0 = (uint32_t)(wm * 64 + mi * 16 + g);
                aq0[mi] = lds128(Ab + r0 * ROWB + kb);
                aq1[mi] = lds128(Ab + (r0 + 8) * ROWB + kb);
            }
            #pragma unroll
            for (int ni = 0; ni < 8; ++ni) {
                const uint32_t rn = (uint32_t)(wn * 64 + ni * 8 + g);
                uint4 bq = lds128(Bb + rn * ROWB + kb);
                #pragma unroll
                for (int mi = 0; mi < 4; ++mi) {
                    uint32_t a0[4] = {aq0[mi].x, aq1[mi].x, aq0[mi].y, aq1[mi].y};
                    uint32_t b0[2] = {bq.x, bq.y};
                    mma8(acc[mi][ni], a0, b0);
                    uint32_t a1[4] = {aq0[mi].z, aq1[mi].z, aq0[mi].w, aq1[mi].w};
                    uint32_t b1[2] = {bq.z, bq.w};
                    mma8(acc[mi][ni], a1, b1);
                }
            }
        }
        if (kt + 2 < NT) {
            __syncthreads();
            issue(kt + 2, buf);
            CP_COMMIT();
        }
    }

    // ---------------- epilogue ----------------
    const bool do_sig = (wsel == sigmoid_wsel);
    #pragma unroll
    for (int mi = 0; mi < 4; ++mi) {
        #pragma unroll
        for (int ni = 0; ni < 8; ++ni) {
            const int row = bm * TM + wm * 64 + mi * 16 + g;
            const int col = bn * TN + wn * 64 + ni * 8 + tg * 2;
            float v0 = acc[mi][ni][0], v1 = acc[mi][ni][1];
            float v2 = acc[mi][ni][2], v3 = acc[mi][ni][3];
            if (do_sig) {
                v0 = 1.f / (1.f + __expf(-v0));
                v1 = 1.f / (1.f + __expf(-v1));
                v2 = 1.f / (1.f + __expf(-v2));
                v3 = 1.f / (1.f + __expf(-v3));
            }
            *reinterpret_cast<float2*>(&O[(size_t)row * CDIM + col])
                = make_float2(v0, v1);
            *reinterpret_cast<float2*>(&O[(size_t)(row + 8) * CDIM + col])
                = make_float2(v2, v3);
        }
    }
}

// ---------------- WKV chunked scan -------------------------------------------
__global__ void wkv_pass1(const float* __restrict__ K, const float* __restrict__ V,
                          const float* __restrict__ td)
{
    const int tix = blockIdx.x * blockDim.x + threadIdx.x;
    const int c = tix & (CDIM - 1);
    const int j = (tix >> 10) & (NCH - 1);
    const int b = tix >> 16;
    const float w = __expf(td[c]);
    const float d = __expf(-w);

    float A = 0.f, Bb = 0.f, m = -3.0e38f;
    size_t off = (size_t)b * TDIM * CDIM + (size_t)j * CLEN * CDIM + c;
    #pragma unroll 8
    for (int t = 0; t < CLEN; ++t, off += CDIM) {
        const float kt = K[off];
        const float vt = V[off];
        const float ek = __expf(kt);
        A  = __fmaf_rn(d, A, ek * vt);
        Bb = __fmaf_rn(d, Bb, ek);
        m  = fmaxf(m - w, kt);
    }
    g_Aloc[tix] = A;
    g_Bloc[tix] = Bb;
    g_Mloc[tix] = m;
}

__global__ void wkv_combine(const float* __restrict__ td,
                            const float* __restrict__ aa0, const float* __restrict__ bb0,
                            const float* __restrict__ pp0,
                            float* __restrict__ st_aa, float* __restrict__ st_bb,
                            float* __restrict__ st_pp)
{
    const int idx = blockIdx.x * blockDim.x + threadIdx.x;
    const int c = idx & (CDIM - 1);
    const int b = idx >> 10;
    const float w  = __expf(td[c]);
    const float dL = __expf(-w * (float)CLEN);
    const float pL = w * (float)CLEN;

    const float p0 = pp0[idx];
    const float e0 = __expf(p0);
    float A  = aa0[idx] * e0;
    float Bb = bb0[idx] * e0;
    float pp = p0;

    const int base = b * (NCH * CDIM) + c;
    #pragma unroll 4
    for (int j = 0; j < NCH; ++j) {
        const int s = base + j * CDIM;
        g_Ain[s] = A;
        g_Bin[s] = Bb;
        A  = __fmaf_rn(dL, A,  g_Aloc[s]);
        Bb = __fmaf_rn(dL, Bb, g_Bloc[s]);
        pp = fmaxf(pp - pL, g_Mloc[s]);
    }
    if (st_aa) {
        const float e = __expf(-pp);
        st_aa[idx] = A * e;
        st_bb[idx] = Bb * e;
        st_pp[idx] = pp;
    }
}

__global__ void wkv_pass2(const float* __restrict__ K, const float* __restrict__ V,
                          float* __restrict__ R,
                          const float* __restrict__ td, const float* __restrict__ tf)
{
    const int tix = blockIdx.x * blockDim.x + threadIdx.x;
    const int c = tix & (CDIM - 1);
    const int j = (tix >> 10) & (NCH - 1);
    const int b = tix >> 16;
    const float w = __expf(td[c]);
    const float u = tf[c];
    const float d = __expf(-w);

    float A  = g_Ain[tix];
    float Bb = g_Bin[tix];

    size_t off = (size_t)b * TDIM * CDIM + (size_t)j * CLEN * CDIM + c;
    #pragma unroll 8
    for (int t = 0; t < CLEN; ++t, off += CDIM) {
        const float kt = K[off];
        const float vt = V[off];
        const float rt = R[off];
        const float eku = __expf(u + kt);
        const float wkv = __fdividef(__fmaf_rn(eku, vt, A), Bb + eku);
        R[off] = f2tff(rt * wkv);          // tf32-rounded for the output GEMM
        const float ek = __expf(kt);
        A  = __fmaf_rn(d, A, ek * vt);
        Bb = __fmaf_rn(d, Bb, ek);
    }
}

// ---------------- launch ----------------
extern "C" void kernel_launch(void* const* d_in, const int* in_sizes, int n_in,
                              void* d_out, int out_size)
{
    const float* x   = (const float*)d_in[0];
    const float* kw  = (const float*)d_in[1];
    const float* vw  = (const float*)d_in[2];
    const float* rw  = (const float*)d_in[3];
    const float* ow  = (const float*)d_in[4];
    const float* td  = (const float*)d_in[5];
    const float* tfi = (const float*)d_in[6];
    const float* aa0 = (const float*)d_in[7];
    const float* bb0 = (const float*)d_in[8];
    const float* pp0 = (const float*)d_in[9];
    float* out = (float*)d_out;

    void *pk, *pv, *pr, *px, *pw;
    cudaGetSymbolAddress(&pk, g_k);
    cudaGetSymbolAddress(&pv, g_v);
    cudaGetSymbolAddress(&pr, g_r);
    cudaGetSymbolAddress(&px, g_x);
    cudaGetSymbolAddress(&pw, g_w);
    float* gk = (float*)pk;
    float* gv = (float*)pv;
    float* gr = (float*)pr;
    float* gx = (float*)px;
    float* gw = (float*)pw;
    const size_t CC = (size_t)CDIM * CDIM;

    cudaFuncSetAttribute(gemm_tc, cudaFuncAttributeMaxDynamicSharedMemorySize, DYN_SMEM);

    const long long BTC = (long long)MDIM * CDIM;
    const int BC = NC;
    const bool write_states = ((long long)out_size >= BTC + 3LL * BC);
    float* staa = write_states ? out + BTC          : nullptr;
    float* stbb = write_states ? out + BTC + BC     : nullptr;
    float* stpp = write_states ? out + BTC + 2 * BC : nullptr;

    // 0) pre-round operands to tf32
    conv_tf32<<<(MDIM * (CDIM/4) + 255) / 256, 256>>>(x, gx, MDIM * (CDIM/4));
    conv_tf32<<<(int)(CC/4 + 255) / 256, 256>>>(kw, gw,            (int)(CC/4));
    conv_tf32<<<(int)(CC/4 + 255) / 256, 256>>>(vw, gw + CC,       (int)(CC/4));
    conv_tf32<<<(int)(CC/4 + 255) / 256, 256>>>(rw, gw + 2*CC,     (int)(CC/4));
    conv_tf32<<<(int)(CC/4 + 255) / 256, 256>>>(ow, gw + 3*CC,     (int)(CC/4));

    // 1) fused k / v / sigmoid(r) projections (3 weights x 4 n-tiles of 256)
    dim3 gp(MDIM / TM, 12);
    gemm_tc<<<gp, 256, DYN_SMEM>>>(gx, gw, gw + CC, gw + 2*CC,
                                   gk, gv, gr, /*sigmoid_wsel=*/2);

    // 2) WKV chunked scan (+ tf32(r*wkv) in place, + final states)
    wkv_pass1 <<<(NC * NCH) / 256, 256>>>(gk, gv, td);
    wkv_combine<<<NC / 256, 256>>>(td, aa0, bb0, pp0, staa, stbb, stpp);
    wkv_pass2 <<<(NC * NCH) / 256, 256>>>(gk, gv, gr, td, tfi);

    // 3) output projection (1 weight x 4 n-tiles)
    dim3 go(MDIM / TM, 4);
    gemm_tc<<<go, 256, DYN_SMEM>>>(gr, gw + 3*CC, gw + 3*CC, gw + 3*CC,
                                   out, out, out, /*sigmoid_wsel=*/-1);
}

// round 7
// speedup vs baseline: 3.4524x; 1.5816x over previous
#include <cuda_runtime.h>
#include <cuda_fp16.h>
#include <cstdint>

#define BDIM 4
#define TDIM 4096
#define CDIM 1024
#define MDIM (BDIM*TDIM)          // 16384 rows
#define KDIM CDIM                 // 1024 reduction
#define NCH  64                   // scan chunks
#define CLEN 64                   // steps per chunk
#define NC   (BDIM*CDIM)          // 4096 channels

// GEMM tiling: block 128x256, 8 warps, warp tile 64x64, BK=32 halves,
// 4-stage cp.async pipeline, fp16 m16n8k16 with fp32 accumulation.
#define TM 128
#define TN 256
#define TBK 32
#define NT (KDIM/TBK)             // 32 k-tiles
#define ROWB 64                   // 32 halves per row = 64B (conflict-free)
#define STA (TM*ROWB)             // 8192 per A stage
#define STB (TN*ROWB)             // 16384 per B stage
#define NSTG 4
#define DYN_SMEM (NSTG*(STA+STB)) // 98304

// ---------------- scratch (static device globals; no allocation) -------------
__device__ float  g_k[(size_t)MDIM*CDIM];
__device__ float  g_v[(size_t)MDIM*CDIM];
__device__ float  g_r[(size_t)MDIM*CDIM];         // sigmoid(r) fp32
__device__ __half g_xh[(size_t)MDIM*CDIM];        // fp16 x
__device__ __half g_wh[4*(size_t)CDIM*CDIM];      // fp16 kw,vw,rw,ow
__device__ __half g_rh[(size_t)MDIM*CDIM];        // fp16 r*wkv
__device__ float  g_Aloc[NC*NCH], g_Bloc[NC*NCH], g_Mloc[NC*NCH];
__device__ float  g_Ain [NC*NCH], g_Bin [NC*NCH];

// ---------------- helpers ----------------
__device__ __forceinline__ uint32_t smem_u32(const void* p) {
    uint32_t a;
    asm("{ .reg .u64 t; cvta.to.shared.u64 t, %1; cvt.u32.u64 %0, t; }" : "=r"(a) : "l"(p));
    return a;
}
__device__ __forceinline__ void mma16(float* d, const uint32_t* a, const uint32_t* b) {
    asm volatile(
        "mma.sync.aligned.m16n8k16.row.col.f32.f16.f16.f32 "
        "{%0,%1,%2,%3}, {%4,%5,%6,%7}, {%8,%9}, {%0,%1,%2,%3};\n"
        : "+f"(d[0]), "+f"(d[1]), "+f"(d[2]), "+f"(d[3])
        : "r"(a[0]), "r"(a[1]), "r"(a[2]), "r"(a[3]), "r"(b[0]), "r"(b[1]));
}
__device__ __forceinline__ uint4 lds128(uint32_t a) {
    uint4 v;
    asm volatile("ld.shared.v4.b32 {%0,%1,%2,%3}, [%4];"
                 : "=r"(v.x), "=r"(v.y), "=r"(v.z), "=r"(v.w) : "r"(a));
    return v;
}
#define CP_ASYNC16(sa, ga) \
    asm volatile("cp.async.cg.shared.global [%0], [%1], 16;" :: "r"(sa), "l"(ga))
#define CP_COMMIT() asm volatile("cp.async.commit_group;" ::: "memory")
#define CP_WAIT2()  asm volatile("cp.async.wait_group 2;" ::: "memory")
#define CP_WAIT1()  asm volatile("cp.async.wait_group 1;" ::: "memory")
#define CP_WAIT0()  asm volatile("cp.async.wait_group 0;" ::: "memory")

// ---------------- fp32 -> fp16 conversion ------------------------------------
__global__ void conv_f2h(const float* __restrict__ in, __half* __restrict__ out, int n4)
{
    const int i = blockIdx.x * blockDim.x + threadIdx.x;
    if (i < n4) {
        float4 v = reinterpret_cast<const float4*>(in)[i];
        __half2 h0 = __floats2half2_rn(v.x, v.y);
        __half2 h1 = __floats2half2_rn(v.z, v.w);
        uint2 p = make_uint2(*reinterpret_cast<uint32_t*>(&h0),
                             *reinterpret_cast<uint32_t*>(&h1));
        reinterpret_cast<uint2*>(out)[i] = p;
    }
}

// ---------------- GEMM: O[m,n] = sum_k A[m,k] * W[n,k]  (fp16 in, fp32 out) --
// 64B smem rows are conflict-free for both cp.async STS (16B chunks across a
// row) and LDS.128 (phase = rows r, r+1 -> disjoint bank halves). One LDS.128
// per row covers k cols 8tg..8tg+7 which feed BOTH m16n8k16 atoms of the
// 32-wide k-tile via k-permutation (A and B use identical col mapping).
__global__ __launch_bounds__(256)
void gemm_fp16(const __half* __restrict__ X,
               const __half* __restrict__ W0, const __half* __restrict__ W1,
               const __half* __restrict__ W2,
               float* __restrict__ O0, float* __restrict__ O1, float* __restrict__ O2,
               int sigmoid_wsel)
{
    extern __shared__ char dyn[];
    const uint32_t sb = smem_u32(dyn);

    const int tid  = threadIdx.x;
    const int lane = tid & 31;
    const int warp = tid >> 5;
    const int wm = warp >> 2;        // 0..1
    const int wn = warp & 3;         // 0..3
    const int g  = lane >> 2;        // 0..7
    const int tg = lane & 3;         // 0..3

    const int bm   = blockIdx.x;
    const int wsel = blockIdx.y >> 2;
    const int bn   = blockIdx.y & 3;

    const __half* Wm = (wsel == 0) ? W0 : ((wsel == 1) ? W1 : W2);
    float*        O  = (wsel == 0) ? O0 : ((wsel == 1) ? O1 : O2);

    const __half* Xt = X  + (size_t)bm * TM * KDIM;
    const __half* Bt = Wm + (size_t)bn * TN * KDIM;

    float acc[4][8][4];
    #pragma unroll
    for (int mi = 0; mi < 4; ++mi)
        #pragma unroll
        for (int ni = 0; ni < 8; ++ni)
            #pragma unroll
            for (int rr = 0; rr < 4; ++rr) acc[mi][ni][rr] = 0.f;

    // --- async load of one k-tile into stage buf ---
    // chunk ch: row = ch>>2, kchunk = ch&3 (16B = 8 halves)
    auto issue = [&](int kt, int buf) {
        const uint32_t sA = sb + buf * (STA + STB);
        const uint32_t sB = sA + STA;
        #pragma unroll
        for (int i = 0; i < 2; ++i) {            // A: 512 chunks / 256 thr
            const int ch = tid + i * 256;
            CP_ASYNC16(sA + ch * 16,
                       Xt + (size_t)(ch >> 2) * KDIM + kt * TBK + (ch & 3) * 8);
        }
        #pragma unroll
        for (int i = 0; i < 4; ++i) {            // B: 1024 chunks / 256 thr
            const int ch = tid + i * 256;
            CP_ASYNC16(sB + ch * 16,
                       Bt + (size_t)(ch >> 2) * KDIM + kt * TBK + (ch & 3) * 8);
        }
    };

    issue(0, 0); CP_COMMIT();
    issue(1, 1); CP_COMMIT();
    issue(2, 2); CP_COMMIT();

    for (int kt = 0; kt < NT; ++kt) {
        const int buf = kt & 3;
        if (kt + 2 < NT) CP_WAIT2();
        else if (kt + 1 < NT) CP_WAIT1();
        else CP_WAIT0();
        __syncthreads();
        if (kt + 3 < NT) { issue(kt + 3, (kt + 3) & 3); CP_COMMIT(); }

        const uint32_t Ab = sb + buf * (STA + STB);
        const uint32_t Bb = Ab + STA;

        uint4 aq0[4], aq1[4];
        #pragma unroll
        for (int mi = 0; mi < 4; ++mi) {
            const uint32_t r0 = (uint32_t)(wm * 64 + mi * 16 + g);
            aq0[mi] = lds128(Ab + r0 * ROWB + tg * 16);
            aq1[mi] = lds128(Ab + (r0 + 8) * ROWB + tg * 16);
        }
        #pragma unroll
        for (int ni = 0; ni < 8; ++ni) {
            const uint32_t rn = (uint32_t)(wn * 64 + ni * 8 + g);
            uint4 bq = lds128(Bb + rn * ROWB + tg * 16);
            #pragma unroll
            for (int mi = 0; mi < 4; ++mi) {
                uint32_t a0[4] = {aq0[mi].x, aq1[mi].x, aq0[mi].y, aq1[mi].y};
                uint32_t b0[2] = {bq.x, bq.y};
                mma16(acc[mi][ni], a0, b0);
                uint32_t a1[4] = {aq0[mi].z, aq1[mi].z, aq0[mi].w, aq1[mi].w};
                uint32_t b1[2] = {bq.z, bq.w};
                mma16(acc[mi][ni], a1, b1);
            }
        }
    }

    // ---------------- epilogue ----------------
    const bool do_sig = (wsel == sigmoid_wsel);
    #pragma unroll
    for (int mi = 0; mi < 4; ++mi) {
        #pragma unroll
        for (int ni = 0; ni < 8; ++ni) {
            const int row = bm * TM + wm * 64 + mi * 16 + g;
            const int col = bn * TN + wn * 64 + ni * 8 + tg * 2;
            float v0 = acc[mi][ni][0], v1 = acc[mi][ni][1];
            float v2 = acc[mi][ni][2], v3 = acc[mi][ni][3];
            if (do_sig) {
                v0 = 1.f / (1.f + __expf(-v0));
                v1 = 1.f / (1.f + __expf(-v1));
                v2 = 1.f / (1.f + __expf(-v2));
                v3 = 1.f / (1.f + __expf(-v3));
            }
            *reinterpret_cast<float2*>(&O[(size_t)row * CDIM + col])
                = make_float2(v0, v1);
            *reinterpret_cast<float2*>(&O[(size_t)(row + 8) * CDIM + col])
                = make_float2(v2, v3);
        }
    }
}

// ---------------- WKV chunked scan -------------------------------------------
__global__ void wkv_pass1(const float* __restrict__ K, const float* __restrict__ V,
                          const float* __restrict__ td)
{
    const int tix = blockIdx.x * blockDim.x + threadIdx.x;
    const int c = tix & (CDIM - 1);
    const int j = (tix >> 10) & (NCH - 1);
    const int b = tix >> 16;
    const float w = __expf(td[c]);
    const float d = __expf(-w);

    float A = 0.f, Bb = 0.f, m = -3.0e38f;
    size_t off = (size_t)b * TDIM * CDIM + (size_t)j * CLEN * CDIM + c;
    #pragma unroll 8
    for (int t = 0; t < CLEN; ++t, off += CDIM) {
        const float kt = K[off];
        const float vt = V[off];
        const float ek = __expf(kt);
        A  = __fmaf_rn(d, A, ek * vt);
        Bb = __fmaf_rn(d, Bb, ek);
        m  = fmaxf(m - w, kt);
    }
    g_Aloc[tix] = A;
    g_Bloc[tix] = Bb;
    g_Mloc[tix] = m;
}

__global__ void wkv_combine(const float* __restrict__ td,
                            const float* __restrict__ aa0, const float* __restrict__ bb0,
                            const float* __restrict__ pp0,
                            float* __restrict__ st_aa, float* __restrict__ st_bb,
                            float* __restrict__ st_pp)
{
    const int idx = blockIdx.x * blockDim.x + threadIdx.x;
    const int c = idx & (CDIM - 1);
    const int b = idx >> 10;
    const float w  = __expf(td[c]);
    const float dL = __expf(-w * (float)CLEN);
    const float pL = w * (float)CLEN;

    const float p0 = pp0[idx];
    const float e0 = __expf(p0);
    float A  = aa0[idx] * e0;
    float Bb = bb0[idx] * e0;
    float pp = p0;

    const int base = b * (NCH * CDIM) + c;
    #pragma unroll 4
    for (int j = 0; j < NCH; ++j) {
        const int s = base + j * CDIM;
        g_Ain[s] = A;
        g_Bin[s] = Bb;
        A  = __fmaf_rn(dL, A,  g_Aloc[s]);
        Bb = __fmaf_rn(dL, Bb, g_Bloc[s]);
        pp = fmaxf(pp - pL, g_Mloc[s]);
    }
    if (st_aa) {
        const float e = __expf(-pp);
        st_aa[idx] = A * e;
        st_bb[idx] = Bb * e;
        st_pp[idx] = pp;
    }
}

__global__ void wkv_pass2(const float* __restrict__ K, const float* __restrict__ V,
                          const float* __restrict__ R, __half* __restrict__ RH,
                          const float* __restrict__ td, const float* __restrict__ tf)
{
    const int tix = blockIdx.x * blockDim.x + threadIdx.x;
    const int c = tix & (CDIM - 1);
    const int j = (tix >> 10) & (NCH - 1);
    const int b = tix >> 16;
    const float w = __expf(td[c]);
    const float u = tf[c];
    const float d = __expf(-w);

    float A  = g_Ain[tix];
    float Bb = g_Bin[tix];

    size_t off = (size_t)b * TDIM * CDIM + (size_t)j * CLEN * CDIM + c;
    #pragma unroll 8
    for (int t = 0; t < CLEN; ++t, off += CDIM) {
        const float kt = K[off];
        const float vt = V[off];
        const float rt = R[off];
        const float eku = __expf(u + kt);
        const float wkv = __fdividef(__fmaf_rn(eku, vt, A), Bb + eku);
        RH[off] = __float2half_rn(rt * wkv);     // fp16 operand for output GEMM
        const float ek = __expf(kt);
        A  = __fmaf_rn(d, A, ek * vt);
        Bb = __fmaf_rn(d, Bb, ek);
    }
}

// ---------------- launch ----------------
extern "C" void kernel_launch(void* const* d_in, const int* in_sizes, int n_in,
                              void* d_out, int out_size)
{
    const float* x   = (const float*)d_in[0];
    const float* kw  = (const float*)d_in[1];
    const float* vw  = (const float*)d_in[2];
    const float* rw  = (const float*)d_in[3];
    const float* ow  = (const float*)d_in[4];
    const float* td  = (const float*)d_in[5];
    const float* tfi = (const float*)d_in[6];
    const float* aa0 = (const float*)d_in[7];
    const float* bb0 = (const float*)d_in[8];
    const float* pp0 = (const float*)d_in[9];
    float* out = (float*)d_out;

    void *pk, *pv, *pr, *pxh, *pwh, *prh;
    cudaGetSymbolAddress(&pk, g_k);
    cudaGetSymbolAddress(&pv, g_v);
    cudaGetSymbolAddress(&pr, g_r);
    cudaGetSymbolAddress(&pxh, g_xh);
    cudaGetSymbolAddress(&pwh, g_wh);
    cudaGetSymbolAddress(&prh, g_rh);
    float*  gk  = (float*)pk;
    float*  gv  = (float*)pv;
    float*  gr  = (float*)pr;
    __half* gxh = (__half*)pxh;
    __half* gwh = (__half*)pwh;
    __half* grh = (__half*)prh;
    const size_t CC = (size_t)CDIM * CDIM;

    cudaFuncSetAttribute(gemm_fp16, cudaFuncAttributeMaxDynamicSharedMemorySize, DYN_SMEM);

    const long long BTC = (long long)MDIM * CDIM;
    const int BC = NC;
    const bool write_states = ((long long)out_size >= BTC + 3LL * BC);
    float* staa = write_states ? out + BTC          : nullptr;
    float* stbb = write_states ? out + BTC + BC     : nullptr;
    float* stpp = write_states ? out + BTC + 2 * BC : nullptr;

    // 0) convert operands to fp16
    conv_f2h<<<(MDIM * (CDIM/4) + 255) / 256, 256>>>(x, gxh, MDIM * (CDIM/4));
    conv_f2h<<<(int)(CC/4 + 255) / 256, 256>>>(kw, gwh,        (int)(CC/4));
    conv_f2h<<<(int)(CC/4 + 255) / 256, 256>>>(vw, gwh + CC,   (int)(CC/4));
    conv_f2h<<<(int)(CC/4 + 255) / 256, 256>>>(rw, gwh + 2*CC, (int)(CC/4));
    conv_f2h<<<(int)(CC/4 + 255) / 256, 256>>>(ow, gwh + 3*CC, (int)(CC/4));

    // 1) fused k / v / sigmoid(r) projections (3 weights x 4 n-tiles of 256)
    dim3 gp(MDIM / TM, 12);
    gemm_fp16<<<gp, 256, DYN_SMEM>>>(gxh, gwh, gwh + CC, gwh + 2*CC,
                                     gk, gv, gr, /*sigmoid_wsel=*/2);

    // 2) WKV chunked scan (+ fp16(r*wkv), + final states)
    wkv_pass1 <<<(NC * NCH) / 256, 256>>>(gk, gv, td);
    wkv_combine<<<NC / 256, 256>>>(td, aa0, bb0, pp0, staa, stbb, stpp);
    wkv_pass2 <<<(NC * NCH) / 256, 256>>>(gk, gv, gr, grh, td, tfi);

    // 3) output projection (1 weight x 4 n-tiles)
    dim3 go(MDIM / TM, 4);
    gemm_fp16<<<go, 256, DYN_SMEM>>>(grh, gwh + 3*CC, gwh + 3*CC, gwh + 3*CC,
                                     out, out, out, /*sigmoid_wsel=*/-1);
}

// round 8
// speedup vs baseline: 4.4043x; 1.2757x over previous
#include <cuda_runtime.h>
#include <cuda_fp16.h>
#include <cstdint>

#define BDIM 4
#define TDIM 4096
#define CDIM 1024
#define MDIM (BDIM*TDIM)          // 16384 rows
#define KDIM CDIM                 // 1024 reduction
#define NCH  64                   // scan chunks
#define CLEN 64                   // steps per chunk
#define NC   (BDIM*CDIM)          // 4096 channels

// GEMM tiling: block 128x128, 8 warps, warp tile 64x32, BK=32 halves,
// 4-stage cp.async pipeline, fp16 m16n8k16 / fp32 accum, 2 CTAs per SM.
#define TM 128
#define TN 128
#define TBK 32
#define NT (KDIM/TBK)             // 32 k-tiles
#define ROWB 64                   // 32 halves per row = 64B (conflict-free)
#define STA (TM*ROWB)             // 8192 per A stage
#define STB (TN*ROWB)             // 8192 per B stage
#define NSTG 4
#define DYN_SMEM (NSTG*(STA+STB)) // 65536

// ---------------- scratch (static device globals; no allocation) -------------
__device__ float  g_k[(size_t)MDIM*CDIM];
__device__ float  g_v[(size_t)MDIM*CDIM];
__device__ float  g_r[(size_t)MDIM*CDIM];         // sigmoid(r) fp32
__device__ __half g_xh[(size_t)MDIM*CDIM];        // fp16 x
__device__ __half g_wh[4*(size_t)CDIM*CDIM];      // fp16 kw,vw,rw,ow
__device__ __half g_rh[(size_t)MDIM*CDIM];        // fp16 r*wkv
__device__ float  g_Aloc[NC*NCH], g_Bloc[NC*NCH], g_Mloc[NC*NCH];
__device__ float  g_Ain [NC*NCH], g_Bin [NC*NCH];

// ---------------- helpers ----------------
__device__ __forceinline__ uint32_t smem_u32(const void* p) {
    uint32_t a;
    asm("{ .reg .u64 t; cvta.to.shared.u64 t, %1; cvt.u32.u64 %0, t; }" : "=r"(a) : "l"(p));
    return a;
}
__device__ __forceinline__ void mma16(float* d, const uint32_t* a, const uint32_t* b) {
    asm volatile(
        "mma.sync.aligned.m16n8k16.row.col.f32.f16.f16.f32 "
        "{%0,%1,%2,%3}, {%4,%5,%6,%7}, {%8,%9}, {%0,%1,%2,%3};\n"
        : "+f"(d[0]), "+f"(d[1]), "+f"(d[2]), "+f"(d[3])
        : "r"(a[0]), "r"(a[1]), "r"(a[2]), "r"(a[3]), "r"(b[0]), "r"(b[1]));
}
__device__ __forceinline__ uint4 lds128(uint32_t a) {
    uint4 v;
    asm volatile("ld.shared.v4.b32 {%0,%1,%2,%3}, [%4];"
                 : "=r"(v.x), "=r"(v.y), "=r"(v.z), "=r"(v.w) : "r"(a));
    return v;
}
#define CP_ASYNC16(sa, ga) \
    asm volatile("cp.async.cg.shared.global [%0], [%1], 16;" :: "r"(sa), "l"(ga))
#define CP_COMMIT() asm volatile("cp.async.commit_group;" ::: "memory")
#define CP_WAIT2()  asm volatile("cp.async.wait_group 2;" ::: "memory")
#define CP_WAIT1()  asm volatile("cp.async.wait_group 1;" ::: "memory")
#define CP_WAIT0()  asm volatile("cp.async.wait_group 0;" ::: "memory")

// ---------------- merged fp32 -> fp16 conversion (x + 4 weights) -------------
#define XF4 (MDIM*(CDIM/4))       // 4194304 float4s of x
#define WF4 ((CDIM*CDIM)/4)       // 262144 float4s per weight
__global__ void conv_all(const float* __restrict__ x,
                         const float* __restrict__ kw, const float* __restrict__ vw,
                         const float* __restrict__ rw, const float* __restrict__ ow,
                         __half* __restrict__ xh, __half* __restrict__ wh)
{
    const int i = blockIdx.x * blockDim.x + threadIdx.x;
    const float4* src;
    uint2* dst;
    int idx;
    if (i < XF4) {
        src = reinterpret_cast<const float4*>(x);
        dst = reinterpret_cast<uint2*>(xh);
        idx = i;
    } else {
        const int j = i - XF4;
        const int seg = j / WF4;               // 0..3
        idx = j - seg * WF4;
        const float* ws = (seg == 0) ? kw : (seg == 1) ? vw : (seg == 2) ? rw : ow;
        src = reinterpret_cast<const float4*>(ws);
        dst = reinterpret_cast<uint2*>(wh) + (size_t)seg * WF4;
    }
    float4 v = src[idx];
    __half2 h0 = __floats2half2_rn(v.x, v.y);
    __half2 h1 = __floats2half2_rn(v.z, v.w);
    dst[idx] = make_uint2(*reinterpret_cast<uint32_t*>(&h0),
                          *reinterpret_cast<uint32_t*>(&h1));
}

// ---------------- GEMM: O[m,n] = sum_k A[m,k] * W[n,k]  (fp16 in, fp32 out) --
// One LDS.128 per row covers k cols 8tg..8tg+7 feeding BOTH m16n8k16 atoms of
// the 32-wide k-tile via k-permutation (A and B use identical col mapping).
__global__ __launch_bounds__(256, 2)
void gemm_fp16(const __half* __restrict__ X,
               const __half* __restrict__ W0, const __half* __restrict__ W1,
               const __half* __restrict__ W2,
               float* __restrict__ O0, float* __restrict__ O1, float* __restrict__ O2,
               int sigmoid_wsel)
{
    extern __shared__ char dyn[];
    const uint32_t sb = smem_u32(dyn);

    const int tid  = threadIdx.x;
    const int lane = tid & 31;
    const int warp = tid >> 5;
    const int wm = warp >> 2;        // 0..1
    const int wn = warp & 3;         // 0..3
    const int g  = lane >> 2;        // 0..7
    const int tg = lane & 3;         // 0..3

    const int bm   = blockIdx.x;
    const int wsel = blockIdx.y >> 3;
    const int bn   = blockIdx.y & 7;

    const __half* Wm = (wsel == 0) ? W0 : ((wsel == 1) ? W1 : W2);
    float*        O  = (wsel == 0) ? O0 : ((wsel == 1) ? O1 : O2);

    const __half* Xt = X  + (size_t)bm * TM * KDIM;
    const __half* Bt = Wm + (size_t)bn * TN * KDIM;

    float acc[4][4][4];
    #pragma unroll
    for (int mi = 0; mi < 4; ++mi)
        #pragma unroll
        for (int ni = 0; ni < 4; ++ni)
            #pragma unroll
            for (int rr = 0; rr < 4; ++rr) acc[mi][ni][rr] = 0.f;

    // --- async load of one k-tile into stage buf ---
    // chunk ch: row = ch>>2, kchunk = ch&3 (16B = 8 halves)
    auto issue = [&](int kt, int buf) {
        const uint32_t sA = sb + buf * (STA + STB);
        const uint32_t sB = sA + STA;
        #pragma unroll
        for (int i = 0; i < 2; ++i) {            // A: 512 chunks / 256 thr
            const int ch = tid + i * 256;
            CP_ASYNC16(sA + ch * 16,
                       Xt + (size_t)(ch >> 2) * KDIM + kt * TBK + (ch & 3) * 8);
        }
        #pragma unroll
        for (int i = 0; i < 2; ++i) {            // B: 512 chunks / 256 thr
            const int ch = tid + i * 256;
            CP_ASYNC16(sB + ch * 16,
                       Bt + (size_t)(ch >> 2) * KDIM + kt * TBK + (ch & 3) * 8);
        }
    };

    issue(0, 0); CP_COMMIT();
    issue(1, 1); CP_COMMIT();
    issue(2, 2); CP_COMMIT();

    for (int kt = 0; kt < NT; ++kt) {
        const int buf = kt & 3;
        if (kt + 2 < NT) CP_WAIT2();
        else if (kt + 1 < NT) CP_WAIT1();
        else CP_WAIT0();
        __syncthreads();
        if (kt + 3 < NT) { issue(kt + 3, (kt + 3) & 3); CP_COMMIT(); }

        const uint32_t Ab = sb + buf * (STA + STB);
        const uint32_t Bb = Ab + STA;

        uint4 aq0[4], aq1[4];
        #pragma unroll
        for (int mi = 0; mi < 4; ++mi) {
            const uint32_t r0 = (uint32_t)(wm * 64 + mi * 16 + g);
            aq0[mi] = lds128(Ab + r0 * ROWB + tg * 16);
            aq1[mi] = lds128(Ab + (r0 + 8) * ROWB + tg * 16);
        }
        #pragma unroll
        for (int ni = 0; ni < 4; ++ni) {
            const uint32_t rn = (uint32_t)(wn * 32 + ni * 8 + g);
            uint4 bq = lds128(Bb + rn * ROWB + tg * 16);
            #pragma unroll
            for (int mi = 0; mi < 4; ++mi) {
                uint32_t a0[4] = {aq0[mi].x, aq1[mi].x, aq0[mi].y, aq1[mi].y};
                uint32_t b0[2] = {bq.x, bq.y};
                mma16(acc[mi][ni], a0, b0);
                uint32_t a1[4] = {aq0[mi].z, aq1[mi].z, aq0[mi].w, aq1[mi].w};
                uint32_t b1[2] = {bq.z, bq.w};
                mma16(acc[mi][ni], a1, b1);
            }
        }
    }

    // ---------------- epilogue ----------------
    const bool do_sig = (wsel == sigmoid_wsel);
    #pragma unroll
    for (int mi = 0; mi < 4; ++mi) {
        #pragma unroll
        for (int ni = 0; ni < 4; ++ni) {
            const int row = bm * TM + wm * 64 + mi * 16 + g;
            const int col = bn * TN + wn * 32 + ni * 8 + tg * 2;
            float v0 = acc[mi][ni][0], v1 = acc[mi][ni][1];
            float v2 = acc[mi][ni][2], v3 = acc[mi][ni][3];
            if (do_sig) {
                v0 = 1.f / (1.f + __expf(-v0));
                v1 = 1.f / (1.f + __expf(-v1));
                v2 = 1.f / (1.f + __expf(-v2));
                v3 = 1.f / (1.f + __expf(-v3));
            }
            *reinterpret_cast<float2*>(&O[(size_t)row * CDIM + col])
                = make_float2(v0, v1);
            *reinterpret_cast<float2*>(&O[(size_t)(row + 8) * CDIM + col])
                = make_float2(v2, v3);
        }
    }
}

// ---------------- WKV chunked scan -------------------------------------------
__global__ void wkv_pass1(const float* __restrict__ K, const float* __restrict__ V,
                          const float* __restrict__ td)
{
    const int tix = blockIdx.x * blockDim.x + threadIdx.x;
    const int c = tix & (CDIM - 1);
    const int j = (tix >> 10) & (NCH - 1);
    const int b = tix >> 16;
    const float w = __expf(td[c]);
    const float d = __expf(-w);

    float A = 0.f, Bb = 0.f, m = -3.0e38f;
    size_t off = (size_t)b * TDIM * CDIM + (size_t)j * CLEN * CDIM + c;
    #pragma unroll 8
    for (int t = 0; t < CLEN; ++t, off += CDIM) {
        const float kt = K[off];
        const float vt = V[off];
        const float ek = __expf(kt);
        A  = __fmaf_rn(d, A, ek * vt);
        Bb = __fmaf_rn(d, Bb, ek);
        m  = fmaxf(m - w, kt);
    }
    g_Aloc[tix] = A;
    g_Bloc[tix] = Bb;
    g_Mloc[tix] = m;
}

__global__ void wkv_combine(const float* __restrict__ td,
                            const float* __restrict__ aa0, const float* __restrict__ bb0,
                            const float* __restrict__ pp0,
                            float* __restrict__ st_aa, float* __restrict__ st_bb,
                            float* __restrict__ st_pp)
{
    const int idx = blockIdx.x * blockDim.x + threadIdx.x;
    const int c = idx & (CDIM - 1);
    const int b = idx >> 10;
    const float w  = __expf(td[c]);
    const float dL = __expf(-w * (float)CLEN);
    const float pL = w * (float)CLEN;

    const float p0 = pp0[idx];
    const float e0 = __expf(p0);
    float A  = aa0[idx] * e0;
    float Bb = bb0[idx] * e0;
    float pp = p0;

    const int base = b * (NCH * CDIM) + c;
    #pragma unroll 4
    for (int j = 0; j < NCH; ++j) {
        const int s = base + j * CDIM;
        g_Ain[s] = A;
        g_Bin[s] = Bb;
        A  = __fmaf_rn(dL, A,  g_Aloc[s]);
        Bb = __fmaf_rn(dL, Bb, g_Bloc[s]);
        pp = fmaxf(pp - pL, g_Mloc[s]);
    }
    if (st_aa) {
        const float e = __expf(-pp);
        st_aa[idx] = A * e;
        st_bb[idx] = Bb * e;
        st_pp[idx] = pp;
    }
}

__global__ void wkv_pass2(const float* __restrict__ K, const float* __restrict__ V,
                          const float* __restrict__ R, __half* __restrict__ RH,
                          const float* __restrict__ td, const float* __restrict__ tf)
{
    const int tix = blockIdx.x * blockDim.x + threadIdx.x;
    const int c = tix & (CDIM - 1);
    const int j = (tix >> 10) & (NCH - 1);
    const int b = tix >> 16;
    const float w = __expf(td[c]);
    const float u = tf[c];
    const float d = __expf(-w);

    float A  = g_Ain[tix];
    float Bb = g_Bin[tix];

    size_t off = (size_t)b * TDIM * CDIM + (size_t)j * CLEN * CDIM + c;
    #pragma unroll 8
    for (int t = 0; t < CLEN; ++t, off += CDIM) {
        const float kt = K[off];
        const float vt = V[off];
        const float rt = R[off];
        const float eku = __expf(u + kt);
        const float wkv = __fdividef(__fmaf_rn(eku, vt, A), Bb + eku);
        RH[off] = __float2half_rn(rt * wkv);     // fp16 operand for output GEMM
        const float ek = __expf(kt);
        A  = __fmaf_rn(d, A, ek * vt);
        Bb = __fmaf_rn(d, Bb, ek);
    }
}

// ---------------- launch ----------------
extern "C" void kernel_launch(void* const* d_in, const int* in_sizes, int n_in,
                              void* d_out, int out_size)
{
    const float* x   = (const float*)d_in[0];
    const float* kw  = (const float*)d_in[1];
    const float* vw  = (const float*)d_in[2];
    const float* rw  = (const float*)d_in[3];
    const float* ow  = (const float*)d_in[4];
    const float* td  = (const float*)d_in[5];
    const float* tfi = (const float*)d_in[6];
    const float* aa0 = (const float*)d_in[7];
    const float* bb0 = (const float*)d_in[8];
    const float* pp0 = (const float*)d_in[9];
    float* out = (float*)d_out;

    void *pk, *pv, *pr, *pxh, *pwh, *prh;
    cudaGetSymbolAddress(&pk, g_k);
    cudaGetSymbolAddress(&pv, g_v);
    cudaGetSymbolAddress(&pr, g_r);
    cudaGetSymbolAddress(&pxh, g_xh);
    cudaGetSymbolAddress(&pwh, g_wh);
    cudaGetSymbolAddress(&prh, g_rh);
    float*  gk  = (float*)pk;
    float*  gv  = (float*)pv;
    float*  gr  = (float*)pr;
    __half* gxh = (__half*)pxh;
    __half* gwh = (__half*)pwh;
    __half* grh = (__half*)prh;
    const size_t CC = (size_t)CDIM * CDIM;

    cudaFuncSetAttribute(gemm_fp16, cudaFuncAttributeMaxDynamicSharedMemorySize, DYN_SMEM);

    const long long BTC = (long long)MDIM * CDIM;
    const int BC = NC;
    const bool write_states = ((long long)out_size >= BTC + 3LL * BC);
    float* staa = write_states ? out + BTC          : nullptr;
    float* stbb = write_states ? out + BTC + BC     : nullptr;
    float* stpp = write_states ? out + BTC + 2 * BC : nullptr;

    // 0) convert all operands to fp16 in one launch
    conv_all<<<(XF4 + 4 * WF4 + 255) / 256, 256>>>(x, kw, vw, rw, ow, gxh, gwh);

    // 1) fused k / v / sigmoid(r) projections (3 weights x 8 n-tiles of 128)
    dim3 gp(MDIM / TM, 24);
    gemm_fp16<<<gp, 256, DYN_SMEM>>>(gxh, gwh, gwh + CC, gwh + 2*CC,
                                     gk, gv, gr, /*sigmoid_wsel=*/2);

    // 2) WKV chunked scan (+ fp16(r*wkv), + final states)
    wkv_pass1 <<<(NC * NCH) / 256, 256>>>(gk, gv, td);
    wkv_combine<<<NC / 256, 256>>>(td, aa0, bb0, pp0, staa, stbb, stpp);
    wkv_pass2 <<<(NC * NCH) / 256, 256>>>(gk, gv, gr, grh, td, tfi);

    // 3) output projection (1 weight x 8 n-tiles)
    dim3 go(MDIM / TM, 8);
    gemm_fp16<<<go, 256, DYN_SMEM>>>(grh, gwh + 3*CC, gwh + 3*CC, gwh + 3*CC,
                                     out, out, out, /*sigmoid_wsel=*/-1);
}